// round 4
// baseline (speedup 1.0000x reference)
#include <cuda_runtime.h>
#include <math.h>

// Problem constants (B=2, N=4096, C=256, K=64; hidden = 256, out = 256)
#define PB 2
#define PN 4096
#define PC 256
#define PK 64
#define THREADS 1024
#define NSL 16              // slices; THREADS / 64 quads

__global__ __launch_bounds__(THREADS)
void roi_fused_kernel(const float* __restrict__ points,        // (B, N, 3)
                      const float* __restrict__ feats,         // (B, N, C)
                      const float* __restrict__ props,         // (B, K, 7)
                      const float* __restrict__ W1,            // (C, 256)
                      const float* __restrict__ b1,            // (256)
                      const float* __restrict__ W2,            // (256, 256)
                      const float* __restrict__ b2,            // (256)
                      float* __restrict__ out)                 // (B, K, 256)
{
    const int bk   = blockIdx.x;        // 0 .. B*K-1
    const int b    = bk / PK;
    const int t    = threadIdx.x;
    const int q    = t & 63;            // channel-quad index (4 channels each)
    const int sl   = t >> 6;            // slice 0..15
    const int lane = t & 31;

    __shared__ int    s_idx[PN];
    __shared__ int    s_count;
    __shared__ float  s_box[6];
    __shared__ float4 s_part[THREADS];  // 16 KB reduction scratch
    __shared__ float4 s_vec[64];        // pooled features (256 floats)
    __shared__ float4 s_h[64];          // hidden activations

    // Warm L2 for this thread's weight lines, overlapped with phases 1-2.
    {
        const char* w1p = (const char*)(W1 + (size_t)(sl * 16) * 256 + q * 4);
        const char* w2p = (const char*)(W2 + (size_t)(sl * 16) * 256 + q * 4);
        #pragma unroll
        for (int c = 0; c < 16; c += 4) {   // every 4th row: 1 line per 1KB span
            asm volatile("prefetch.global.L2 [%0];" :: "l"(w1p + c * 1024));
            asm volatile("prefetch.global.L2 [%0];" :: "l"(w2p + c * 1024));
        }
    }

    if (t == 0) s_count = 0;
    if (t < 3) {
        float c = props[bk * 7 + t];
        float h = props[bk * 7 + 3 + t] * 0.5f;
        s_box[t]     = c - h;   // lo
        s_box[t + 3] = c + h;   // hi
    }
    __syncthreads();

    const float lx = s_box[0], ly = s_box[1], lz = s_box[2];
    const float hx = s_box[3], hy = s_box[4], hz = s_box[5];

    // ---- Phase 1: warp-aggregated compaction of inside-point indices ----
    const float* pb = points + (size_t)b * PN * 3;
    #pragma unroll
    for (int it = 0; it < PN / THREADS; it++) {
        int n = it * THREADS + t;
        float px = pb[n * 3 + 0];
        float py = pb[n * 3 + 1];
        float pz = pb[n * 3 + 2];
        bool inside = (px > lx) & (px < hx) &
                      (py > ly) & (py < hy) &
                      (pz > lz) & (pz < hz);
        unsigned m = __ballot_sync(0xffffffffu, inside);
        if (m) {
            int base = 0;
            if (lane == 0) base = atomicAdd(&s_count, __popc(m));
            base = __shfl_sync(0xffffffffu, base, 0);
            if (inside) {
                int off = __popc(m & ((1u << lane) - 1u));
                s_idx[base + off] = n;
            }
        }
    }
    __syncthreads();
    const int cnt = s_count;

    // ---- Phase 2: max-pool; 16 slices stride the inside list, float4 lanes ----
    const float4* fb4 = (const float4*)(feats + (size_t)b * PN * PC);
    float4 acc = make_float4(-INFINITY, -INFINITY, -INFINITY, -INFINITY);
    {
        int i = sl;
        for (; i + 3 * NSL < cnt; i += 4 * NSL) {
            int n0 = s_idx[i + 0 * NSL];
            int n1 = s_idx[i + 1 * NSL];
            int n2 = s_idx[i + 2 * NSL];
            int n3 = s_idx[i + 3 * NSL];
            float4 v0 = fb4[(size_t)n0 * 64 + q];
            float4 v1 = fb4[(size_t)n1 * 64 + q];
            float4 v2 = fb4[(size_t)n2 * 64 + q];
            float4 v3 = fb4[(size_t)n3 * 64 + q];
            acc.x = fmaxf(acc.x, fmaxf(fmaxf(v0.x, v1.x), fmaxf(v2.x, v3.x)));
            acc.y = fmaxf(acc.y, fmaxf(fmaxf(v0.y, v1.y), fmaxf(v2.y, v3.y)));
            acc.z = fmaxf(acc.z, fmaxf(fmaxf(v0.z, v1.z), fmaxf(v2.z, v3.z)));
            acc.w = fmaxf(acc.w, fmaxf(fmaxf(v0.w, v1.w), fmaxf(v2.w, v3.w)));
        }
        for (; i < cnt; i += NSL) {
            float4 v = fb4[(size_t)s_idx[i] * 64 + q];
            acc.x = fmaxf(acc.x, v.x);
            acc.y = fmaxf(acc.y, v.y);
            acc.z = fmaxf(acc.z, v.z);
            acc.w = fmaxf(acc.w, v.w);
        }
    }
    s_part[t] = acc;
    __syncthreads();

    // single-stage reduce: 64 threads fold all 16 slices (max)
    if (t < 64) {
        float4 a = s_part[t];
        #pragma unroll
        for (int g = 1; g < NSL; g++) {
            float4 c = s_part[g * 64 + t];
            a.x = fmaxf(a.x, c.x);
            a.y = fmaxf(a.y, c.y);
            a.z = fmaxf(a.z, c.z);
            a.w = fmaxf(a.w, c.w);
        }
        if (cnt == 0) a = make_float4(0.f, 0.f, 0.f, 0.f);
        s_vec[t] = a;
    }
    __syncthreads();

    // ---- Phase 3: h = relu(pooled @ W1 + b1); slice sl covers c in [16*sl, 16*sl+16) ----
    {
        const float4* W1_4 = (const float4*)W1;
        const float*  vecf = (const float*)s_vec;
        float4 ha = make_float4(0.f, 0.f, 0.f, 0.f);
        const int c0 = sl * 16;
        #pragma unroll
        for (int c = 0; c < 16; c++) {
            float f = vecf[c0 + c];                  // warp-uniform broadcast
            float4 w = W1_4[(size_t)(c0 + c) * 64 + q];
            ha.x = fmaf(f, w.x, ha.x);
            ha.y = fmaf(f, w.y, ha.y);
            ha.z = fmaf(f, w.z, ha.z);
            ha.w = fmaf(f, w.w, ha.w);
        }
        s_part[t] = ha;
    }
    __syncthreads();
    if (t < 64) {
        float4 a = s_part[t];
        #pragma unroll
        for (int g = 1; g < NSL; g++) {
            float4 c = s_part[g * 64 + t];
            a.x += c.x; a.y += c.y; a.z += c.z; a.w += c.w;
        }
        float4 bb = ((const float4*)b1)[t];
        a.x = fmaxf(a.x + bb.x, 0.f);
        a.y = fmaxf(a.y + bb.y, 0.f);
        a.z = fmaxf(a.z + bb.z, 0.f);
        a.w = fmaxf(a.w + bb.w, 0.f);
        s_h[t] = a;
    }
    __syncthreads();

    // ---- Phase 4: out = relu(h @ W2 + b2) ----
    {
        const float4* W2_4 = (const float4*)W2;
        const float*  hf = (const float*)s_h;
        float4 oa = make_float4(0.f, 0.f, 0.f, 0.f);
        const int c0 = sl * 16;
        #pragma unroll
        for (int c = 0; c < 16; c++) {
            float f = hf[c0 + c];
            float4 w = W2_4[(size_t)(c0 + c) * 64 + q];
            oa.x = fmaf(f, w.x, oa.x);
            oa.y = fmaf(f, w.y, oa.y);
            oa.z = fmaf(f, w.z, oa.z);
            oa.w = fmaf(f, w.w, oa.w);
        }
        s_part[t] = oa;
    }
    __syncthreads();
    if (t < 64) {
        float4 a = s_part[t];
        #pragma unroll
        for (int g = 1; g < NSL; g++) {
            float4 c = s_part[g * 64 + t];
            a.x += c.x; a.y += c.y; a.z += c.z; a.w += c.w;
        }
        float4 bb = ((const float4*)b2)[t];
        a.x = fmaxf(a.x + bb.x, 0.f);
        a.y = fmaxf(a.y + bb.y, 0.f);
        a.z = fmaxf(a.z + bb.z, 0.f);
        a.w = fmaxf(a.w + bb.w, 0.f);
        ((float4*)out)[(size_t)bk * 64 + t] = a;
    }
}

extern "C" void kernel_launch(void* const* d_in, const int* in_sizes, int n_in,
                              void* d_out, int out_size)
{
    const float* points = (const float*)d_in[0];   // (B, N, 3)
    const float* feats  = (const float*)d_in[1];   // (B, N, C)
    const float* props  = (const float*)d_in[2];   // (B, K, 7)
    const float* W1     = (const float*)d_in[3];   // (C, 256)
    const float* b1     = (const float*)d_in[4];   // (256)
    const float* W2     = (const float*)d_in[5];   // (256, 256)
    const float* b2     = (const float*)d_in[6];   // (256)
    float*       out    = (float*)d_out;           // (B, K, 256)

    roi_fused_kernel<<<PB * PK, THREADS>>>(points, feats, props, W1, b1, W2, b2, out);
}